// round 2
// baseline (speedup 1.0000x reference)
#include <cuda_runtime.h>
#include <math.h>

#define LQ   512
#define DSD  384
#define DPD  256
#define NH   12
#define AD   16
#define NQ   4
#define NV   8
#define HA   192   // NH*AD
#define HQ3  144   // NH*NQ*3
#define HV3  288   // NH*NV*3
#define SHD  3648  // NH*(DPD+AD+3*NV+NV)
#define PH   304   // per-head shid slice
#define EPSL 1e-5f
#define WCC  0.23570226039551584f  // sqrt(2/(9*Q)) = sqrt(1/18)
#define WLC  0.5773502691896258f   // sqrt(1/3)
#define RCH  456                   // SHD / 8

// ---------------- scratch (device globals; no allocation) ----------------
__device__ float g_q[LQ * HA];
__device__ float g_k[LQ * HA];
__device__ float g_v[LQ * HA];
__device__ float g_qp[LQ * HQ3];
__device__ float g_kp[LQ * HQ3];
__device__ float g_vp[LQ * HV3];
__device__ float g_qpn[LQ * NH];
__device__ float g_kpn[LQ * NH];
__device__ float g_rot[LQ * 9];
__device__ float g_attn[(size_t)LQ * NH * LQ];   // [i][h][j]; logits then softmax in-place
__device__ float g_shid[(size_t)LQ * SHD];
__device__ float g_part[(size_t)8 * LQ * DSD];
__device__ float g_s[LQ * DSD];
__device__ float g_sln[LQ * DSD];
__device__ float g_h1[LQ * DSD];
__device__ float g_h2[LQ * DSD];

// ---------------- K1: projections + frames + point norms ----------------
__global__ void proj_kernel(const float* __restrict__ sfea, const float* __restrict__ quat,
                            const float* __restrict__ trsl,
                            const float* __restrict__ Wq, const float* __restrict__ Wk,
                            const float* __restrict__ Wv, const float* __restrict__ Wqp,
                            const float* __restrict__ Wkp, const float* __restrict__ Wvp) {
  const int i = blockIdx.x;
  const int t = threadIdx.x;  // 384
  __shared__ float s_row[DSD];
  __shared__ float s_raw[1152];   // [0:144) qp, [144:288) kp, [288:576) vp (local frame)
  __shared__ float s_rot[9];
  __shared__ float s_pts[576];    // 192 points x 3 (global frame)
  s_row[t] = sfea[i * DSD + t];
  if (t == 0) {
    float qx = quat[i * 3], qy = quat[i * 3 + 1], qz = quat[i * 3 + 2];
    float inv = rsqrtf(1.f + qx * qx + qy * qy + qz * qz);
    float w = inv, x = qx * inv, y = qy * inv, z = qz * inv;
    s_rot[0] = 1.f - 2.f * (y * y + z * z); s_rot[1] = 2.f * (x * y - w * z); s_rot[2] = 2.f * (x * z + w * y);
    s_rot[3] = 2.f * (x * y + w * z); s_rot[4] = 1.f - 2.f * (x * x + z * z); s_rot[5] = 2.f * (y * z - w * x);
    s_rot[6] = 2.f * (x * z - w * y); s_rot[7] = 2.f * (y * z + w * x); s_rot[8] = 1.f - 2.f * (x * x + y * y);
#pragma unroll
    for (int r = 0; r < 9; r++) g_rot[i * 9 + r] = s_rot[r];
  }
  __syncthreads();
#pragma unroll
  for (int rep = 0; rep < 3; rep++) {
    int o = t + rep * 384;  // 0..1151
    const float* W; int col, ncol;
    if (o < 192)      { W = Wq;  col = o;       ncol = HA; }
    else if (o < 384) { W = Wk;  col = o - 192; ncol = HA; }
    else if (o < 576) { W = Wv;  col = o - 384; ncol = HA; }
    else if (o < 720) { W = Wqp; col = o - 576; ncol = HQ3; }
    else if (o < 864) { W = Wkp; col = o - 720; ncol = HQ3; }
    else              { W = Wvp; col = o - 864; ncol = HV3; }
    float acc = 0.f;
    for (int r = 0; r < DSD; r++) acc += s_row[r] * W[r * ncol + col];
    if (o < 192)      g_q[i * HA + col] = acc;
    else if (o < 384) g_k[i * HA + col] = acc;
    else if (o < 576) g_v[i * HA + col] = acc;
    else              s_raw[o - 576] = acc;
  }
  __syncthreads();
  if (t < 192) {  // apply frame to each point
    float tx = trsl[i * 3], ty = trsl[i * 3 + 1], tz = trsl[i * 3 + 2];
    float px = s_raw[t * 3], py = s_raw[t * 3 + 1], pz = s_raw[t * 3 + 2];
    float gx = s_rot[0] * px + s_rot[1] * py + s_rot[2] * pz + tx;
    float gy = s_rot[3] * px + s_rot[4] * py + s_rot[5] * pz + ty;
    float gz = s_rot[6] * px + s_rot[7] * py + s_rot[8] * pz + tz;
    s_pts[t * 3] = gx; s_pts[t * 3 + 1] = gy; s_pts[t * 3 + 2] = gz;
    float* dst;
    if (t < 48)      dst = &g_qp[i * HQ3 + t * 3];
    else if (t < 96) dst = &g_kp[i * HQ3 + (t - 48) * 3];
    else             dst = &g_vp[i * HV3 + (t - 96) * 3];
    dst[0] = gx; dst[1] = gy; dst[2] = gz;
  }
  __syncthreads();
  if (t < 24) {  // per-head squared norms of the 12-dim point vectors
    int h = t % NH; bool isK = (t >= NH);
    const float* base = &s_pts[(isK ? 144 : 0) + h * 12];
    float n = 0.f;
#pragma unroll
    for (int c = 0; c < 12; c++) n += base[c] * base[c];
    if (isK) g_kpn[i * NH + h] = n; else g_qpn[i * NH + h] = n;
  }
}

// ---------------- K2: attention logits (bias GEMM + qk + point distances) ----------------
// Block = query i. Thread t owns j = {2t, 2t+1} x all 12 heads (24 accumulators).
__global__ void __launch_bounds__(256) logits_kernel(const float* __restrict__ pfea,
                                                     const float* __restrict__ Wb,
                                                     const float* __restrict__ scale) {
  const int i = blockIdx.x;
  const int t = threadIdx.x;  // 256
  __shared__ float s_p[16 * 513];                  // p-major tile [16 p][512 j], padded
  __shared__ __align__(16) float s_wbT[NH * DPD];  // Wb transposed: [h][p]
  __shared__ float s_q[HA];
  __shared__ float s_qpv[HQ3];
  __shared__ float s_qpn[NH];
  __shared__ float s_c[NH];

  for (int idx = t; idx < NH * DPD; idx += 256) {
    int h = idx >> 8, p = idx & 255;
    s_wbT[idx] = Wb[p * NH + h];
  }
  if (t < HA)  s_q[t]   = g_q[i * HA + t];
  if (t < HQ3) s_qpv[t] = g_qp[i * HQ3 + t];
  if (t < NH) {
    s_qpn[t] = g_qpn[i * NH + t];
    float sc = scale[t];
    float sp = (sc > 20.f) ? sc : log1pf(expf(sc));
    s_c[t] = WCC * sp * 0.5f;
  }
  __syncthreads();

  float acc[2][NH];
#pragma unroll
  for (int jj = 0; jj < 2; jj++)
#pragma unroll
    for (int h = 0; h < NH; h++) acc[jj][h] = 0.f;

  const float* prow = pfea + (size_t)i * LQ * DPD;

  for (int p0 = 0; p0 < DPD; p0 += 16) {
    for (int idx = t; idx < 16 * LQ; idx += 256) {
      int j = idx >> 4, p = idx & 15;
      s_p[p * 513 + j] = prow[(size_t)j * DPD + p0 + p];
    }
    __syncthreads();
#pragma unroll
    for (int pp = 0; pp < 16; pp += 4) {
      float wv[NH][4];
#pragma unroll
      for (int h = 0; h < NH; h++) {
        float4 w4 = *(const float4*)&s_wbT[h * DPD + p0 + pp];
        wv[h][0] = w4.x; wv[h][1] = w4.y; wv[h][2] = w4.z; wv[h][3] = w4.w;
      }
#pragma unroll
      for (int q = 0; q < 4; q++) {
        float a0 = s_p[(pp + q) * 513 + 2 * t];
        float a1 = s_p[(pp + q) * 513 + 2 * t + 1];
#pragma unroll
        for (int h = 0; h < NH; h++) {
          acc[0][h] += a0 * wv[h][q];
          acc[1][h] += a1 * wv[h][q];
        }
      }
    }
    __syncthreads();
  }

#pragma unroll
  for (int jj = 0; jj < 2; jj++) {
    int j = 2 * t + jj;
#pragma unroll
    for (int h = 0; h < NH; h++) {
      float qk = 0.f;
      const float* kr = &g_k[j * HA + h * AD];
      const float* qr = &s_q[h * AD];
#pragma unroll
      for (int d = 0; d < AD; d++) qk += qr[d] * kr[d];
      float dotp = 0.f;
      const float* kpv = &g_kp[j * HQ3 + h * 12];
      const float* qpv = &s_qpv[h * 12];
#pragma unroll
      for (int c = 0; c < 12; c++) dotp += qpv[c] * kpv[c];
      float d2 = s_qpn[h] + g_kpn[j * NH + h] - 2.f * dotp;
      float logit = WLC * (qk * 0.25f + acc[jj][h] - s_c[h] * d2);
      g_attn[((size_t)i * NH + h) * LQ + j] = logit;
    }
  }
}

// ---------------- K3: softmax over j per (i,h) row ----------------
__global__ void softmax_kernel() {
  const int row = blockIdx.x;  // i*NH + h
  float* x = &g_attn[(size_t)row * LQ];
  const int t = threadIdx.x;  // 256
  __shared__ float red[256];
  float v0 = x[t], v1 = x[t + 256];
  red[t] = fmaxf(v0, v1);
  __syncthreads();
  for (int s = 128; s > 0; s >>= 1) { if (t < s) red[t] = fmaxf(red[t], red[t + s]); __syncthreads(); }
  float m = red[0];
  __syncthreads();
  float e0 = expf(v0 - m), e1 = expf(v1 - m);
  red[t] = e0 + e1;
  __syncthreads();
  for (int s = 128; s > 0; s >>= 1) { if (t < s) red[t] += red[t + s]; __syncthreads(); }
  float inv = 1.f / red[0];
  x[t] = e0 * inv;
  x[t + 256] = e1 * inv;
}

// ---------------- K4: op[i,h,p] = sum_j a[i,h,j] * pfea[i,j,p] ----------------
__global__ void op_kernel(const float* __restrict__ pfea) {
  const int i = blockIdx.x;
  const int t = threadIdx.x;  // 256 (p column)
  __shared__ __align__(16) float s_a[NH * LQ];
  for (int idx = t; idx < NH * LQ; idx += 256) s_a[idx] = g_attn[(size_t)i * NH * LQ + idx];
  __syncthreads();
  float acc[NH];
#pragma unroll
  for (int h = 0; h < NH; h++) acc[h] = 0.f;
  const float* prow = pfea + (size_t)i * LQ * DPD + t;
  for (int j4 = 0; j4 < LQ; j4 += 4) {
    float p0 = prow[(size_t)(j4 + 0) * DPD];
    float p1 = prow[(size_t)(j4 + 1) * DPD];
    float p2 = prow[(size_t)(j4 + 2) * DPD];
    float p3 = prow[(size_t)(j4 + 3) * DPD];
#pragma unroll
    for (int h = 0; h < NH; h++) {
      float4 av = *(const float4*)&s_a[h * LQ + j4];
      acc[h] += av.x * p0 + av.y * p1 + av.z * p2 + av.w * p3;
    }
  }
#pragma unroll
  for (int h = 0; h < NH; h++) g_shid[(size_t)i * SHD + h * PH + t] = acc[h];
}

// ---------------- K5: ov, ovp (inverse frame) + norms ----------------
__global__ void ovp_kernel(const float* __restrict__ trsl) {
  const int i = blockIdx.x;
  const int t = threadIdx.x;  // 480
  __shared__ float s_a[NH * LQ];
  __shared__ float s_w[HV3];
  __shared__ float s_o[HV3];
  for (int idx = t; idx < NH * LQ; idx += 480) s_a[idx] = g_attn[(size_t)i * NH * LQ + idx];
  __syncthreads();
  float acc = 0.f;
  if (t < HA) {
    const int h = t / AD;
    const float* ar = &s_a[h * LQ];
#pragma unroll 4
    for (int j = 0; j < LQ; j++) acc += ar[j] * g_v[j * HA + t];
    g_shid[(size_t)i * SHD + h * PH + DPD + (t - h * AD)] = acc;
  } else if (t < HA + HV3) {
    const int o = t - HA;
    const int h = o / 24;
    const float* ar = &s_a[h * LQ];
#pragma unroll 4
    for (int j = 0; j < LQ; j++) acc += ar[j] * g_vp[j * HV3 + o];
    s_w[o] = acc;
  }
  __syncthreads();
  if (t < HV3) {
    int h = t / 24, rem = t % 24, vv = rem / 3, c = rem % 3;
    float w0 = s_w[h * 24 + vv * 3 + 0] - trsl[i * 3 + 0];
    float w1 = s_w[h * 24 + vv * 3 + 1] - trsl[i * 3 + 1];
    float w2 = s_w[h * 24 + vv * 3 + 2] - trsl[i * 3 + 2];
    // ovp[...,c] = sum_j rot[l][j][c] * w[j]  (inverse rotation)
    float val = g_rot[i * 9 + 0 + c] * w0 + g_rot[i * 9 + 3 + c] * w1 + g_rot[i * 9 + 6 + c] * w2;
    g_shid[(size_t)i * SHD + h * PH + DPD + AD + rem] = val;
    s_o[t] = val;
  }
  __syncthreads();
  if (t < NH * NV) {
    int h = t / NV, vv = t % NV;
    float a0 = s_o[h * 24 + vv * 3], a1 = s_o[h * 24 + vv * 3 + 1], a2 = s_o[h * 24 + vv * 3 + 2];
    g_shid[(size_t)i * SHD + h * PH + DPD + AD + 24 + vv] = sqrtf(a0 * a0 + a1 * a1 + a2 * a2);
  }
}

// ---------------- K6: shid @ Ws, split 8-way over the 3648 reduction dim ----------------
__global__ void gemm_ws_partial(const float* __restrict__ Ws) {
  const int rt = blockIdx.x, ch = blockIdx.y;  // 64 x 8
  const int t = threadIdx.x;                   // 384 (output column)
  __shared__ __align__(16) float s_x[8 * RCH];
  const int i0 = rt * 8, r0 = ch * RCH;
  for (int idx = t; idx < 8 * RCH; idx += 384) {
    int rr = idx / RCH, r = idx % RCH;
    s_x[idx] = g_shid[(size_t)(i0 + rr) * SHD + r0 + r];
  }
  __syncthreads();
  float acc[8] = {0, 0, 0, 0, 0, 0, 0, 0};
  for (int r = 0; r < RCH; r += 4) {
    float w0 = Ws[(size_t)(r0 + r + 0) * DSD + t];
    float w1 = Ws[(size_t)(r0 + r + 1) * DSD + t];
    float w2 = Ws[(size_t)(r0 + r + 2) * DSD + t];
    float w3 = Ws[(size_t)(r0 + r + 3) * DSD + t];
#pragma unroll
    for (int rr = 0; rr < 8; rr++) {
      float4 xv = *(const float4*)&s_x[rr * RCH + r];
      acc[rr] += xv.x * w0 + xv.y * w1 + xv.z * w2 + xv.w * w3;
    }
  }
#pragma unroll
  for (int rr = 0; rr < 8; rr++)
    g_part[((size_t)ch * LQ + i0 + rr) * DSD + t] = acc[rr];
}

__global__ void reduce_ws(const float* __restrict__ sfea, const float* __restrict__ bs) {
  const int i = blockIdx.x, t = threadIdx.x;  // 512 x 384
  float v = sfea[i * DSD + t] + bs[t];
#pragma unroll
  for (int ch = 0; ch < 8; ch++) v += g_part[((size_t)ch * LQ + i) * DSD + t];
  g_s[i * DSD + t] = v;
}

// ---------------- LayerNorm ----------------
__global__ void ln_kernel(const float* __restrict__ in, const float* __restrict__ g,
                          const float* __restrict__ b, float* __restrict__ out) {
  const int i = blockIdx.x, t = threadIdx.x;  // 512 x 384
  __shared__ float sh[DSD];
  __shared__ float s_m, s_v;
  float x = in[i * DSD + t];
  sh[t] = x;
  __syncthreads();
  for (int s = 192; s >= 3; s >>= 1) { if (t < s) sh[t] += sh[t + s]; __syncthreads(); }
  if (t == 0) s_m = (sh[0] + sh[1] + sh[2]) * (1.f / 384.f);
  __syncthreads();
  float d = x - s_m;
  sh[t] = d * d;
  __syncthreads();
  for (int s = 192; s >= 3; s >>= 1) { if (t < s) sh[t] += sh[t + s]; __syncthreads(); }
  if (t == 0) s_v = (sh[0] + sh[1] + sh[2]) * (1.f / 384.f);
  __syncthreads();
  out[i * DSD + t] = d * rsqrtf(s_v + EPSL) * g[t] + b[t];
}

// ---------------- 384x384 GEMM (+bias, +optional residual, +optional relu) ----------------
__global__ void gemm384_kernel(const float* __restrict__ X, const float* __restrict__ W,
                               const float* __restrict__ bias, const float* __restrict__ res,
                               float* __restrict__ out, int relu) {
  const int rt = blockIdx.x, t = threadIdx.x;  // 64 x 384
  __shared__ __align__(16) float s_x[8 * DSD];
  const int i0 = rt * 8;
  for (int idx = t; idx < 8 * DSD; idx += 384) s_x[idx] = X[(size_t)i0 * DSD + idx];
  __syncthreads();
  float acc[8] = {0, 0, 0, 0, 0, 0, 0, 0};
  for (int r = 0; r < DSD; r += 4) {
    float w0 = W[(r + 0) * DSD + t];
    float w1 = W[(r + 1) * DSD + t];
    float w2 = W[(r + 2) * DSD + t];
    float w3 = W[(r + 3) * DSD + t];
#pragma unroll
    for (int rr = 0; rr < 8; rr++) {
      float4 xv = *(const float4*)&s_x[rr * DSD + r];
      acc[rr] += xv.x * w0 + xv.y * w1 + xv.z * w2 + xv.w * w3;
    }
  }
#pragma unroll
  for (int rr = 0; rr < 8; rr++) {
    float vv = acc[rr] + bias[t];
    if (res) vv += res[(size_t)(i0 + rr) * DSD + t];
    if (relu) vv = fmaxf(vv, 0.f);
    out[(size_t)(i0 + rr) * DSD + t] = vv;
  }
}

// ---------------- launch ----------------
extern "C" void kernel_launch(void* const* d_in, const int* in_sizes, int n_in,
                              void* d_out, int out_size) {
  const float* sfea  = (const float*)d_in[0];
  const float* pfea  = (const float*)d_in[1];
  const float* quat  = (const float*)d_in[2];
  const float* trsl  = (const float*)d_in[3];
  const float* Wq    = (const float*)d_in[4];
  const float* Wk    = (const float*)d_in[5];
  const float* Wv    = (const float*)d_in[6];
  const float* Wqp   = (const float*)d_in[7];
  const float* Wkp   = (const float*)d_in[8];
  const float* Wvp   = (const float*)d_in[9];
  const float* Wb    = (const float*)d_in[10];
  const float* scale = (const float*)d_in[11];
  const float* Ws    = (const float*)d_in[12];
  const float* bs    = (const float*)d_in[13];
  const float* W1    = (const float*)d_in[14];
  const float* b1    = (const float*)d_in[15];
  const float* W2    = (const float*)d_in[16];
  const float* b2    = (const float*)d_in[17];
  const float* W3    = (const float*)d_in[18];
  const float* b3    = (const float*)d_in[19];
  const float* g1    = (const float*)d_in[20];
  const float* be1   = (const float*)d_in[21];
  const float* g2    = (const float*)d_in[22];
  const float* be2   = (const float*)d_in[23];
  float* out = (float*)d_out;

  // host-side symbol address queries (no device work, capture-safe)
  float *p_s, *p_sln, *p_h1, *p_h2;
  cudaGetSymbolAddress((void**)&p_s,   g_s);
  cudaGetSymbolAddress((void**)&p_sln, g_sln);
  cudaGetSymbolAddress((void**)&p_h1,  g_h1);
  cudaGetSymbolAddress((void**)&p_h2,  g_h2);

  proj_kernel<<<LQ, 384>>>(sfea, quat, trsl, Wq, Wk, Wv, Wqp, Wkp, Wvp);
  logits_kernel<<<LQ, 256>>>(pfea, Wb, scale);
  softmax_kernel<<<LQ * NH, 256>>>();
  op_kernel<<<LQ, 256>>>(pfea);
  ovp_kernel<<<LQ, 480>>>(trsl);
  dim3 gws(64, 8);
  gemm_ws_partial<<<gws, 384>>>(Ws);
  reduce_ws<<<LQ, 384>>>(sfea, bs);
  ln_kernel<<<LQ, DSD>>>(p_s, g1, be1, p_sln);
  gemm384_kernel<<<64, 384>>>(p_sln, W1, b1, nullptr, p_h1, 1);
  gemm384_kernel<<<64, 384>>>(p_h1, W2, b2, nullptr, p_h2, 1);
  gemm384_kernel<<<64, 384>>>(p_h2, W3, b3, p_sln, p_s, 0);
  ln_kernel<<<LQ, DSD>>>(p_s, g2, be2, out);
}

// round 5
// speedup vs baseline: 1.9833x; 1.9833x over previous
#include <cuda_runtime.h>
#include <math.h>

#define LQ   512
#define DSD  384
#define DPD  256
#define NH   12
#define AD   16
#define NQ   4
#define NV   8
#define HA   192
#define HQ3  144
#define HV3  288
#define SHD  3648
#define PH   304
#define EPSL 1e-5f
#define WCC  0.23570226039551584f
#define WLC  0.5773502691896258f
#define RCH  456                   // SHD/8

// ---------------- scratch ----------------
__device__ float g_proj[LQ * 1152];        // [i][c]: q(0) k(192) v(384) qp(576) kp(720) vp(864) (local frame for points)
__device__ float g_kT[HA * LQ];            // [c][j]  (coalesced for logits)
__device__ float g_kpT[HQ3 * LQ];          // [c][j]  global-frame k points
__device__ float g_kpnT[NH * LQ];          // [h][j]
__device__ float g_qp[LQ * HQ3];           // [i][c]  global-frame q points
__device__ float g_vp[LQ * HV3];           // [i][c]  global-frame v points
__device__ float g_qpn[LQ * NH];
__device__ float g_rot[LQ * 9];
__device__ float g_shid[(size_t)LQ * SHD];
__device__ float g_part[(size_t)8 * LQ * DSD];
__device__ float g_sln[LQ * DSD];
__device__ float g_h1[LQ * DSD];
__device__ float g_h2[LQ * DSD];
__device__ float g_s2[LQ * DSD];

// ---------------- K1: projection GEMM (512x1152x384) ----------------
__device__ __forceinline__ void resolve_col(int c, const float*& W, int& ncol, int& col,
    const float* Wq, const float* Wk, const float* Wv,
    const float* Wqp, const float* Wkp, const float* Wvp) {
  if (c < 192)      { W = Wq;  ncol = HA;  col = c; }
  else if (c < 384) { W = Wk;  ncol = HA;  col = c - 192; }
  else if (c < 576) { W = Wv;  ncol = HA;  col = c - 384; }
  else if (c < 720) { W = Wqp; ncol = HQ3; col = c - 576; }
  else if (c < 864) { W = Wkp; ncol = HQ3; col = c - 720; }
  else              { W = Wvp; ncol = HV3; col = c - 864; }
}

__global__ void __launch_bounds__(384) proj_gemm(const float* __restrict__ sfea,
    const float* __restrict__ Wq, const float* __restrict__ Wk, const float* __restrict__ Wv,
    const float* __restrict__ Wqp, const float* __restrict__ Wkp, const float* __restrict__ Wvp) {
  const int i0 = blockIdx.x * 8;
  const int t = threadIdx.x;
  __shared__ __align__(16) float s_x[8 * DSD];
  for (int idx = t; idx < 8 * DSD; idx += 384) s_x[idx] = sfea[(size_t)i0 * DSD + idx];
  __syncthreads();
  const float *W0, *W1, *W2; int n0, n1, n2, c0, c1, c2;
  resolve_col(t,       W0, n0, c0, Wq, Wk, Wv, Wqp, Wkp, Wvp);
  resolve_col(t + 384, W1, n1, c1, Wq, Wk, Wv, Wqp, Wkp, Wvp);
  resolve_col(t + 768, W2, n2, c2, Wq, Wk, Wv, Wqp, Wkp, Wvp);
  float a0[8] = {0}, a1[8] = {0}, a2[8] = {0};
  for (int r = 0; r < DSD; r += 4) {
    float w0a = W0[(r + 0) * n0 + c0], w0b = W0[(r + 1) * n0 + c0], w0c = W0[(r + 2) * n0 + c0], w0d = W0[(r + 3) * n0 + c0];
    float w1a = W1[(r + 0) * n1 + c1], w1b = W1[(r + 1) * n1 + c1], w1c = W1[(r + 2) * n1 + c1], w1d = W1[(r + 3) * n1 + c1];
    float w2a = W2[(r + 0) * n2 + c2], w2b = W2[(r + 1) * n2 + c2], w2c = W2[(r + 2) * n2 + c2], w2d = W2[(r + 3) * n2 + c2];
#pragma unroll
    for (int rr = 0; rr < 8; rr++) {
      float4 xv = *(const float4*)&s_x[rr * DSD + r];
      a0[rr] += xv.x * w0a + xv.y * w0b + xv.z * w0c + xv.w * w0d;
      a1[rr] += xv.x * w1a + xv.y * w1b + xv.z * w1c + xv.w * w1d;
      a2[rr] += xv.x * w2a + xv.y * w2b + xv.z * w2c + xv.w * w2d;
    }
  }
#pragma unroll
  for (int rr = 0; rr < 8; rr++) {
    g_proj[(size_t)(i0 + rr) * 1152 + t]       = a0[rr];
    g_proj[(size_t)(i0 + rr) * 1152 + t + 384] = a1[rr];
    g_proj[(size_t)(i0 + rr) * 1152 + t + 768] = a2[rr];
  }
}

// ---------------- K2: frames, point transforms, transposes, norms ----------------
__global__ void __launch_bounds__(192) frame_kernel(const float* __restrict__ quat,
                                                    const float* __restrict__ trsl) {
  const int i = blockIdx.x;
  const int t = threadIdx.x;  // 192
  __shared__ float s_rot[9];
  __shared__ float s_pts[288];  // 96 q/k points x 3 (global frame)
  if (t == 0) {
    float qx = quat[i * 3], qy = quat[i * 3 + 1], qz = quat[i * 3 + 2];
    float inv = rsqrtf(1.f + qx * qx + qy * qy + qz * qz);
    float w = inv, x = qx * inv, y = qy * inv, z = qz * inv;
    s_rot[0] = 1.f - 2.f * (y * y + z * z); s_rot[1] = 2.f * (x * y - w * z); s_rot[2] = 2.f * (x * z + w * y);
    s_rot[3] = 2.f * (x * y + w * z); s_rot[4] = 1.f - 2.f * (x * x + z * z); s_rot[5] = 2.f * (y * z - w * x);
    s_rot[6] = 2.f * (x * z - w * y); s_rot[7] = 2.f * (y * z + w * x); s_rot[8] = 1.f - 2.f * (x * x + y * y);
#pragma unroll
    for (int r = 0; r < 9; r++) g_rot[i * 9 + r] = s_rot[r];
  }
  // k transpose (no rotation): coalesced read, strided write
  g_kT[t * LQ + i] = g_proj[(size_t)i * 1152 + 192 + t];
  __syncthreads();
  // transform the 192 points (48 qp, 48 kp, 96 vp)
  {
    float tx = trsl[i * 3], ty = trsl[i * 3 + 1], tz = trsl[i * 3 + 2];
    int base = (t < 48) ? (576 + t * 3) : (t < 96 ? (720 + (t - 48) * 3) : (864 + (t - 96) * 3));
    float px = g_proj[(size_t)i * 1152 + base];
    float py = g_proj[(size_t)i * 1152 + base + 1];
    float pz = g_proj[(size_t)i * 1152 + base + 2];
    float gx = s_rot[0] * px + s_rot[1] * py + s_rot[2] * pz + tx;
    float gy = s_rot[3] * px + s_rot[4] * py + s_rot[5] * pz + ty;
    float gz = s_rot[6] * px + s_rot[7] * py + s_rot[8] * pz + tz;
    if (t < 48) {
      g_qp[i * HQ3 + t * 3] = gx; g_qp[i * HQ3 + t * 3 + 1] = gy; g_qp[i * HQ3 + t * 3 + 2] = gz;
      s_pts[t * 3] = gx; s_pts[t * 3 + 1] = gy; s_pts[t * 3 + 2] = gz;
    } else if (t < 96) {
      int o = (t - 48) * 3;
      g_kpT[(o + 0) * LQ + i] = gx; g_kpT[(o + 1) * LQ + i] = gy; g_kpT[(o + 2) * LQ + i] = gz;
      s_pts[144 + o] = gx; s_pts[144 + o + 1] = gy; s_pts[144 + o + 2] = gz;
    } else {
      int o = (t - 96) * 3;
      g_vp[i * HV3 + o] = gx; g_vp[i * HV3 + o + 1] = gy; g_vp[i * HV3 + o + 2] = gz;
    }
  }
  __syncthreads();
  if (t < 24) {
    int h = t % NH; bool isK = (t >= NH);
    const float* base = &s_pts[(isK ? 144 : 0) + h * 12];
    float n = 0.f;
#pragma unroll
    for (int c = 0; c < 12; c++) n += base[c] * base[c];
    if (isK) g_kpnT[h * LQ + i] = n; else g_qpn[i * NH + h] = n;
  }
}

// ---------------- K3: fused attention (logits + softmax + op + ov + ovp) ----------------
__global__ void __launch_bounds__(512) attn_fused(const float* __restrict__ pfea,
                                                  const float* __restrict__ Wb,
                                                  const float* __restrict__ scale,
                                                  const float* __restrict__ trsl) {
  const int i = blockIdx.x;
  const int t = threadIdx.x;  // 512
  __shared__ __align__(16) float buf1[16 * 513];   // pass1 p-tile, then attn a[12][512]
  __shared__ __align__(16) float buf2[NH * 256];   // WbT [h][p], then op half-sum buffer
  __shared__ float s_q[HA], s_qpv[HQ3], s_qpn[NH], s_c[NH];
  __shared__ float s_w[HV3], s_o[HV3], s_rot[9], s_t[3];

  for (int idx = t; idx < NH * 256; idx += 512) {
    int h = idx >> 8, p = idx & 255;
    buf2[idx] = Wb[p * NH + h];
  }
  if (t < HA)  s_q[t]   = g_proj[(size_t)i * 1152 + t];
  if (t < HQ3) s_qpv[t] = g_qp[i * HQ3 + t];
  if (t < NH) {
    s_qpn[t] = g_qpn[i * NH + t];
    float sc = scale[t];
    float sp = (sc > 20.f) ? sc : log1pf(expf(sc));
    s_c[t] = WCC * sp * 0.5f;
  }
  if (t < 9) s_rot[t] = g_rot[i * 9 + t];
  if (t < 3) s_t[t] = trsl[i * 3 + t];
  __syncthreads();

  // ---- pass 1: logits (thread t owns j = t, 12 head accumulators) ----
  float acc[NH];
#pragma unroll
  for (int h = 0; h < NH; h++) acc[h] = 0.f;
  const float* prow = pfea + (size_t)i * LQ * DPD;

  for (int p0 = 0; p0 < DPD; p0 += 16) {
    for (int idx = t; idx < 16 * LQ; idx += 512) {
      int j = idx >> 4, p = idx & 15;
      buf1[p * 513 + j] = prow[(size_t)j * DPD + p0 + p];
    }
    __syncthreads();
#pragma unroll
    for (int pp = 0; pp < 16; pp += 4) {
      float v0 = buf1[(pp + 0) * 513 + t];
      float v1 = buf1[(pp + 1) * 513 + t];
      float v2 = buf1[(pp + 2) * 513 + t];
      float v3 = buf1[(pp + 3) * 513 + t];
#pragma unroll
      for (int h = 0; h < NH; h++) {
        float4 w4 = *(const float4*)&buf2[h * 256 + p0 + pp];
        acc[h] += v0 * w4.x + v1 * w4.y + v2 * w4.z + v3 * w4.w;
      }
    }
    __syncthreads();
  }

  // qk + point-distance terms (coalesced via transposed layouts)
#pragma unroll
  for (int h = 0; h < NH; h++) {
    float qk = 0.f;
#pragma unroll
    for (int d = 0; d < AD; d++) qk += s_q[h * AD + d] * g_kT[(h * AD + d) * LQ + t];
    float dp = 0.f;
#pragma unroll
    for (int c = 0; c < 12; c++) dp += s_qpv[h * 12 + c] * g_kpT[(h * 12 + c) * LQ + t];
    float d2 = s_qpn[h] + g_kpnT[h * LQ + t] - 2.f * dp;
    acc[h] = WLC * (qk * 0.25f + acc[h] - s_c[h] * d2);
  }
  // store logits into buf1 as a[12][512]
#pragma unroll
  for (int h = 0; h < NH; h++) buf1[h * LQ + t] = acc[h];
  __syncthreads();

  // ---- softmax: warp w handles head w ----
  {
    int w = t >> 5, lane = t & 31;
    if (w < NH) {
      float* row = &buf1[w * LQ];
      float m = -1e30f;
#pragma unroll
      for (int j = 0; j < 16; j++) m = fmaxf(m, row[lane + j * 32]);
#pragma unroll
      for (int o = 16; o > 0; o >>= 1) m = fmaxf(m, __shfl_xor_sync(0xffffffffu, m, o));
      float e[16]; float s = 0.f;
#pragma unroll
      for (int j = 0; j < 16; j++) { e[j] = expf(row[lane + j * 32] - m); s += e[j]; }
#pragma unroll
      for (int o = 16; o > 0; o >>= 1) s += __shfl_xor_sync(0xffffffffu, s, o);
      float inv = 1.f / s;
#pragma unroll
      for (int j = 0; j < 16; j++) row[lane + j * 32] = e[j] * inv;
    }
  }
  __syncthreads();

  // ---- pass 2a: op[h][p] = sum_j a[h][j] * pfea[j][p]; split j into two halves ----
  {
    const int half = t >> 8, p = t & 255;
    float oa[NH];
#pragma unroll
    for (int h = 0; h < NH; h++) oa[h] = 0.f;
    const float* pr2 = prow + (size_t)half * 256 * DPD + p;
    const int jb = half * 256;
    for (int j4 = 0; j4 < 256; j4 += 4) {
      float p0 = pr2[(size_t)(j4 + 0) * DPD];
      float p1 = pr2[(size_t)(j4 + 1) * DPD];
      float p2 = pr2[(size_t)(j4 + 2) * DPD];
      float p3 = pr2[(size_t)(j4 + 3) * DPD];
#pragma unroll
      for (int h = 0; h < NH; h++) {
        float4 av = *(const float4*)&buf1[h * LQ + jb + j4];
        oa[h] += av.x * p0 + av.y * p1 + av.z * p2 + av.w * p3;
      }
    }
    __syncthreads();  // buf2 (WbT) no longer needed
    if (half == 1) {
#pragma unroll
      for (int h = 0; h < NH; h++) buf2[h * 256 + p] = oa[h];
    }
    __syncthreads();
    if (half == 0) {
#pragma unroll
      for (int h = 0; h < NH; h++)
        g_shid[(size_t)i * SHD + h * PH + p] = oa[h] + buf2[h * 256 + p];
    }
  }

  // ---- pass 2b: ov (t<192) and ovp raw (192<=t<480) ----
  {
    float a0 = 0.f, a1 = 0.f;
    if (t < HA) {
      const int h = t / AD;
      const float* ar = &buf1[h * LQ];
      const float* vcol = &g_proj[384 + t];
      for (int j = 0; j < LQ; j += 2) {
        a0 += ar[j] * vcol[(size_t)j * 1152];
        a1 += ar[j + 1] * vcol[(size_t)(j + 1) * 1152];
      }
      g_shid[(size_t)i * SHD + h * PH + DPD + (t - h * AD)] = a0 + a1;
    } else if (t < HA + HV3) {
      const int o = t - HA;
      const int h = o / 24;
      const float* ar = &buf1[h * LQ];
      const float* vpc = &g_vp[o];
      for (int j = 0; j < LQ; j += 2) {
        a0 += ar[j] * vpc[(size_t)j * HV3];
        a1 += ar[j + 1] * vpc[(size_t)(j + 1) * HV3];
      }
      s_w[o] = a0 + a1;
    }
  }
  __syncthreads();
  if (t < HV3) {
    int h = t / 24, rem = t % 24, vv = rem / 3, c = rem % 3;
    float w0 = s_w[h * 24 + vv * 3 + 0] - s_t[0];
    float w1 = s_w[h * 24 + vv * 3 + 1] - s_t[1];
    float w2 = s_w[h * 24 + vv * 3 + 2] - s_t[2];
    float val = s_rot[0 + c] * w0 + s_rot[3 + c] * w1 + s_rot[6 + c] * w2;
    g_shid[(size_t)i * SHD + h * PH + DPD + AD + rem] = val;
    s_o[t] = val;
  }
  __syncthreads();
  if (t < NH * NV) {
    int h = t / NV, vv = t % NV;
    float b0 = s_o[h * 24 + vv * 3], b1 = s_o[h * 24 + vv * 3 + 1], b2 = s_o[h * 24 + vv * 3 + 2];
    g_shid[(size_t)i * SHD + h * PH + DPD + AD + 24 + vv] = sqrtf(b0 * b0 + b1 * b1 + b2 * b2);
  }
}

// ---------------- K4: shid @ Ws, 16 rows/block, 8-way reduction split ----------------
__global__ void __launch_bounds__(384) gemm_ws_partial(const float* __restrict__ Ws) {
  const int rt = blockIdx.x, ch = blockIdx.y;  // 32 x 8
  const int t = threadIdx.x;                   // 384
  __shared__ __align__(16) float s_x[16 * RCH];
  const int i0 = rt * 16, r0 = ch * RCH;
  for (int idx = t; idx < 16 * RCH; idx += 384) {
    int rr = idx / RCH, r = idx % RCH;
    s_x[idx] = g_shid[(size_t)(i0 + rr) * SHD + r0 + r];
  }
  __syncthreads();
  float acc[16];
#pragma unroll
  for (int rr = 0; rr < 16; rr++) acc[rr] = 0.f;
  for (int r = 0; r < RCH; r += 4) {
    float w0 = Ws[(size_t)(r0 + r + 0) * DSD + t];
    float w1 = Ws[(size_t)(r0 + r + 1) * DSD + t];
    float w2 = Ws[(size_t)(r0 + r + 2) * DSD + t];
    float w3 = Ws[(size_t)(r0 + r + 3) * DSD + t];
#pragma unroll
    for (int rr = 0; rr < 16; rr++) {
      float4 xv = *(const float4*)&s_x[rr * RCH + r];
      acc[rr] += xv.x * w0 + xv.y * w1 + xv.z * w2 + xv.w * w3;
    }
  }
#pragma unroll
  for (int rr = 0; rr < 16; rr++)
    g_part[((size_t)ch * LQ + i0 + rr) * DSD + t] = acc[rr];
}

// ---------------- K5: reduce partials + residual + LN1 -> g_sln ----------------
__global__ void __launch_bounds__(384) reduce_ln(const float* __restrict__ sfea,
                                                 const float* __restrict__ bs,
                                                 const float* __restrict__ g,
                                                 const float* __restrict__ b) {
  const int i = blockIdx.x, t = threadIdx.x;
  float x = sfea[i * DSD + t] + bs[t];
#pragma unroll
  for (int ch = 0; ch < 8; ch++) x += g_part[((size_t)ch * LQ + i) * DSD + t];
  __shared__ float sh[DSD];
  __shared__ float s_m, s_v;
  sh[t] = x;
  __syncthreads();
  for (int s = 192; s >= 3; s >>= 1) { if (t < s) sh[t] += sh[t + s]; __syncthreads(); }
  if (t == 0) s_m = (sh[0] + sh[1] + sh[2]) * (1.f / 384.f);
  __syncthreads();
  float d = x - s_m;
  sh[t] = d * d;
  __syncthreads();
  for (int s = 192; s >= 3; s >>= 1) { if (t < s) sh[t] += sh[t + s]; __syncthreads(); }
  if (t == 0) s_v = (sh[0] + sh[1] + sh[2]) * (1.f / 384.f);
  __syncthreads();
  g_sln[i * DSD + t] = d * rsqrtf(s_v + EPSL) * g[t] + b[t];
}

// ---------------- LayerNorm (generic) ----------------
__global__ void __launch_bounds__(384) ln_kernel(const float* __restrict__ in, const float* __restrict__ g,
                                                 const float* __restrict__ b, float* __restrict__ out) {
  const int i = blockIdx.x, t = threadIdx.x;
  __shared__ float sh[DSD];
  __shared__ float s_m, s_v;
  float x = in[i * DSD + t];
  sh[t] = x;
  __syncthreads();
  for (int s = 192; s >= 3; s >>= 1) { if (t < s) sh[t] += sh[t + s]; __syncthreads(); }
  if (t == 0) s_m = (sh[0] + sh[1] + sh[2]) * (1.f / 384.f);
  __syncthreads();
  float d = x - s_m;
  sh[t] = d * d;
  __syncthreads();
  for (int s = 192; s >= 3; s >>= 1) { if (t < s) sh[t] += sh[t + s]; __syncthreads(); }
  if (t == 0) s_v = (sh[0] + sh[1] + sh[2]) * (1.f / 384.f);
  __syncthreads();
  out[i * DSD + t] = d * rsqrtf(s_v + EPSL) * g[t] + b[t];
}

// ---------------- 384x384 GEMM, 8 rows/block (64 blocks) ----------------
__global__ void __launch_bounds__(384) gemm384_kernel(const float* __restrict__ X, const float* __restrict__ W,
                               const float* __restrict__ bias, const float* __restrict__ res,
                               float* __restrict__ out, int relu) {
  const int i0 = blockIdx.x * 8, t = threadIdx.x;
  __shared__ __align__(16) float s_x[8 * DSD];
  for (int idx = t; idx < 8 * DSD; idx += 384) s_x[idx] = X[(size_t)i0 * DSD + idx];
  __syncthreads();
  float acc[8] = {0, 0, 0, 0, 0, 0, 0, 0};
  for (int r = 0; r < DSD; r += 4) {
    float w0 = W[(r + 0) * DSD + t];
    float w1 = W[(r + 1) * DSD + t];
    float w2 = W[(r + 2) * DSD + t];
    float w3 = W[(r + 3) * DSD + t];
#pragma unroll
    for (int rr = 0; rr < 8; rr++) {
      float4 xv = *(const float4*)&s_x[rr * DSD + r];
      acc[rr] += xv.x * w0 + xv.y * w1 + xv.z * w2 + xv.w * w3;
    }
  }
#pragma unroll
  for (int rr = 0; rr < 8; rr++) {
    float vv = acc[rr] + bias[t];
    if (res) vv += res[(size_t)(i0 + rr) * DSD + t];
    if (relu) vv = fmaxf(vv, 0.f);
    out[(size_t)(i0 + rr) * DSD + t] = vv;
  }
}

// ---------------- launch ----------------
extern "C" void kernel_launch(void* const* d_in, const int* in_sizes, int n_in,
                              void* d_out, int out_size) {
  const float* sfea  = (const float*)d_in[0];
  const float* pfea  = (const float*)d_in[1];
  const float* quat  = (const float*)d_in[2];
  const float* trsl  = (const float*)d_in[3];
  const float* Wq    = (const float*)d_in[4];
  const float* Wk    = (const float*)d_in[5];
  const float* Wv    = (const float*)d_in[6];
  const float* Wqp   = (const float*)d_in[7];
  const float* Wkp   = (const float*)d_in[8];
  const float* Wvp   = (const float*)d_in[9];
  const float* Wb    = (const float*)d_in[10];
  const float* scale = (const float*)d_in[11];
  const float* Ws    = (const float*)d_in[12];
  const float* bs    = (const float*)d_in[13];
  const float* W1    = (const float*)d_in[14];
  const float* b1    = (const float*)d_in[15];
  const float* W2    = (const float*)d_in[16];
  const float* b2    = (const float*)d_in[17];
  const float* W3    = (const float*)d_in[18];
  const float* b3    = (const float*)d_in[19];
  const float* g1    = (const float*)d_in[20];
  const float* be1   = (const float*)d_in[21];
  const float* g2    = (const float*)d_in[22];
  const float* be2   = (const float*)d_in[23];
  float* out = (float*)d_out;

  float *p_sln, *p_h1, *p_h2, *p_s2;
  cudaGetSymbolAddress((void**)&p_sln, g_sln);
  cudaGetSymbolAddress((void**)&p_h1,  g_h1);
  cudaGetSymbolAddress((void**)&p_h2,  g_h2);
  cudaGetSymbolAddress((void**)&p_s2,  g_s2);

  proj_gemm<<<64, 384>>>(sfea, Wq, Wk, Wv, Wqp, Wkp, Wvp);
  frame_kernel<<<LQ, 192>>>(quat, trsl);
  attn_fused<<<LQ, 512>>>(pfea, Wb, scale, trsl);
  dim3 gws(32, 8);
  gemm_ws_partial<<<gws, 384>>>(Ws);
  reduce_ln<<<LQ, 384>>>(sfea, bs, g1, be1);
  gemm384_kernel<<<64, 384>>>(p_sln, W1, b1, nullptr, p_h1, 1);
  gemm384_kernel<<<64, 384>>>(p_h1, W2, b2, nullptr, p_h2, 1);
  gemm384_kernel<<<64, 384>>>(p_h2, W3, b3, p_sln, p_s2, 0);
  ln_kernel<<<LQ, 384>>>(p_s2, g2, be2, out);
}